// round 11
// baseline (speedup 1.0000x reference)
#include <cuda_runtime.h>
#include <cuda_fp16.h>
#include <cstdint>
#include <math.h>

// ---------------------------------------------------------------------------
// Problem constants
// ---------------------------------------------------------------------------
namespace {
constexpr int HID     = 2048;
constexpr int QK_NOPE = 128;
constexpr int QK_ROPE = 64;
constexpr int QK_HEAD = QK_NOPE + QK_ROPE;        // 192
constexpr int Q_LR    = 768;
constexpr int KV_LR   = 512;
constexpr int NH      = 16;
constexpr int V_DIM   = 128;
constexpr int Bb      = 2;
constexpr int Ss      = 4096;
constexpr int Mrows   = Bb * Ss;                  // 8192
constexpr int QD      = NH * QK_HEAD;             // 3072
constexpr int KVD     = NH * (QK_NOPE + V_DIM);   // 4096
constexpr int KVC_D   = KV_LR + QK_ROPE;          // 576
constexpr int OUT_D   = 512;
}

// ---------------------------------------------------------------------------
// Device scratch
// ---------------------------------------------------------------------------
__device__ float  g_qc  [Mrows * Q_LR];
__device__ float  g_kvc [Mrows * KVC_D];
__device__ __half g_qch [Mrows * Q_LR];
__device__ __half g_kvch[Mrows * KV_LR];
__device__ __half g_hidh[Mrows * HID];
__device__ __half g_wqah [Q_LR * HID];
__device__ __half g_wqbh [QD * Q_LR];
__device__ __half g_wkvah[KVC_D * HID];
__device__ __half g_wkvbh[KVD * KV_LR];
__device__ float  g_cos [Ss * 32];
__device__ float  g_sin [Ss * 32];

// ---------------------------------------------------------------------------
// Helpers
// ---------------------------------------------------------------------------
__device__ __forceinline__ uint32_t smem_u32(const void* p) {
    uint32_t a;
    asm("{ .reg .u64 t; cvta.to.shared.u64 t, %1; cvt.u32.u64 %0, t; }"
        : "=r"(a) : "l"(p));
    return a;
}

__device__ __forceinline__ void cp_async16(uint32_t dst, const void* src, bool valid) {
    int sz = valid ? 16 : 0;
    asm volatile("cp.async.ca.shared.global [%0], [%1], 16, %2;"
                 :: "r"(dst), "l"(src), "r"(sz) : "memory");
}
__device__ __forceinline__ void cp_commit() {
    asm volatile("cp.async.commit_group;" ::: "memory");
}
template <int N>
__device__ __forceinline__ void cp_wait() {
    asm volatile("cp.async.wait_group %0;" :: "n"(N) : "memory");
}

__device__ __forceinline__ void ldsm4(uint32_t& r0, uint32_t& r1,
                                      uint32_t& r2, uint32_t& r3, uint32_t addr) {
    asm volatile("ldmatrix.sync.aligned.m8n8.x4.shared.b16 {%0,%1,%2,%3}, [%4];"
                 : "=r"(r0), "=r"(r1), "=r"(r2), "=r"(r3) : "r"(addr));
}

__device__ __forceinline__ void mma16(float* c,
                                      uint32_t a0, uint32_t a1, uint32_t a2, uint32_t a3,
                                      uint32_t b0, uint32_t b1) {
    asm volatile(
        "mma.sync.aligned.m16n8k16.row.col.f32.f16.f16.f32 "
        "{%0,%1,%2,%3}, {%4,%5,%6,%7}, {%8,%9}, {%0,%1,%2,%3};"
        : "+f"(c[0]), "+f"(c[1]), "+f"(c[2]), "+f"(c[3])
        : "r"(a0), "r"(a1), "r"(a2), "r"(a3), "r"(b0), "r"(b1));
}

__device__ __forceinline__ void conv_chunk(const float4* __restrict__ src,
                                           uint2* __restrict__ dst, int chunk) {
    int base = chunk * 2048 + threadIdx.x;
#pragma unroll
    for (int j = 0; j < 8; ++j) {
        int idx = base + j * 256;
        float4 v = src[idx];
        __half2 h0 = __floats2half2_rn(v.x, v.y);
        __half2 h1 = __floats2half2_rn(v.z, v.w);
        dst[idx] = make_uint2(*(uint32_t*)&h0, *(uint32_t*)&h1);
    }
}

// ---------------------------------------------------------------------------
// GEMM config: block 128x128x32, 256 threads, 8 warps (4M x 2N), warp tile
// 32x64, 3-stage cp.async, 2 CTAs/SM.
// ---------------------------------------------------------------------------
namespace {
constexpr int BM = 128;
constexpr int BN = 128;
constexpr int BK = 32;
constexpr int NSTAGE = 3;
constexpr int LDSH = 40;
constexpr int A_ST_H = BM * LDSH;
constexpr int B_ST_H = BN * LDSH;
constexpr int STAGE_H = A_ST_H + B_ST_H;              // 10240 halves
constexpr uint32_t GEMM_SMEM = NSTAGE * STAGE_H * 2;  // 61440 B
}

enum { EPI_PLAIN = 0, EPI_Q = 1, EPI_KV = 2 };

struct GemmDesc {
    const __half* A;  int lda;
    const __half* B;  int ldb;
    const float*  bias;
    float*        C;  int ldc;
    int N, K, mode;
};

struct ConvDesc {
    const float4* src;
    uint2*        dst;
    int           nblk;     // chunks of 2048 float4
};

// Flattened 1D grid: [0, nbx*mb) GEMM tiles (x-major), then conversion CTAs.
__global__ void __launch_bounds__(256, 2)
gemm_mma_f16_dual(GemmDesc d0, GemmDesc d1, int split, int nbx, int mb,
                  ConvDesc c0, ConvDesc c1)
{
    extern __shared__ __half smh[];
    const uint32_t sm_b = smem_u32(smh);

    const int bid = blockIdx.x;
    const int ngemm = nbx * mb;
    if (bid >= ngemm) {
        // tail-filler: fp32->fp16 conversion chunks for the next stage
        int cbid = bid - ngemm;
        if (cbid < c0.nblk) conv_chunk(c0.src, c0.dst, cbid);
        else                conv_chunk(c1.src, c1.dst, cbid - c0.nblk);
        return;
    }

    const int bxi = bid % nbx;
    const int byi = bid / nbx;

    const GemmDesc& D = (bxi < split) ? d0 : d1;
    const int bn = ((bxi < split) ? bxi : (bxi - split)) * BN;
    const __half* __restrict__ A = D.A;
    const __half* __restrict__ B = D.B;
    const int lda = D.lda, ldb = D.ldb, N = D.N, K = D.K, MODE = D.mode;

    const int tid  = threadIdx.x;
    const int wid  = tid >> 5;
    const int lane = tid & 31;
    const int wm   = wid & 3;
    const int wn   = wid >> 2;
    const int bm   = byi * BM;
    const int m0   = wm * 32;
    const int n0   = wn * 64;
    const int qr   = lane >> 2;
    const int qc   = lane & 3;

    const int aRow  = m0 + (lane & 15);
    const int aKoff = (lane >> 4) * 8;
    const int bRow  = n0 + ((lane >> 4) & 1) * 8 + (lane & 7);
    const int bKoff = ((lane >> 3) & 1) * 8;

    float acc[2][8][4];
#pragma unroll
    for (int i = 0; i < 2; i++)
#pragma unroll
        for (int j = 0; j < 8; j++)
#pragma unroll
            for (int k = 0; k < 4; k++) acc[i][j][k] = 0.f;

    const int T = K / BK;

    auto issue_stage = [&](int t) {
        const int buf = t % NSTAGE;
        const uint32_t aBase = sm_b + (uint32_t)buf * STAGE_H * 2;
        const uint32_t bBase = aBase + A_ST_H * 2;
        const int k0 = t * BK;
#pragma unroll
        for (int j = 0; j < 2; ++j) {
            int i = j * 256 + tid;
            int r = i >> 2, c8 = i & 3;
            cp_async16(aBase + (uint32_t)(r * LDSH * 2 + c8 * 16),
                       A + (size_t)(bm + r) * lda + k0 + c8 * 8, true);
        }
#pragma unroll
        for (int j = 0; j < 2; ++j) {
            int i = j * 256 + tid;
            int r = i >> 2, c8 = i & 3;
            int n = bn + r;
            cp_async16(bBase + (uint32_t)(r * LDSH * 2 + c8 * 16),
                       B + (size_t)(n < N ? n : 0) * ldb + k0 + c8 * 8, n < N);
        }
        cp_commit();
    };

#pragma unroll
    for (int i = 0; i < NSTAGE - 1; ++i)
        if (i < T) issue_stage(i);

    for (int t = 0; t < T; ++t) {
        if (t < T - 1) cp_wait<NSTAGE - 2>(); else cp_wait<0>();
        __syncthreads();
        if (t + NSTAGE - 1 < T) issue_stage(t + NSTAGE - 1);

        const uint32_t As_u = sm_b + (uint32_t)(t % NSTAGE) * STAGE_H * 2;
        const uint32_t Bs_u = As_u + A_ST_H * 2;

#pragma unroll
        for (int kk = 0; kk < 2; ++kk) {
            const int kb = kk * 16;
            uint32_t a[2][4];
#pragma unroll
            for (int mf = 0; mf < 2; ++mf)
                ldsm4(a[mf][0], a[mf][1], a[mf][2], a[mf][3],
                      As_u + (uint32_t)((aRow + mf * 16) * LDSH + kb + aKoff) * 2);
            uint32_t b[8][2];
#pragma unroll
            for (int nfp = 0; nfp < 4; ++nfp)
                ldsm4(b[2 * nfp][0], b[2 * nfp][1], b[2 * nfp + 1][0], b[2 * nfp + 1][1],
                      Bs_u + (uint32_t)((bRow + nfp * 16) * LDSH + kb + bKoff) * 2);
#pragma unroll
            for (int nf = 0; nf < 8; ++nf)
#pragma unroll
                for (int mf = 0; mf < 2; ++mf)
                    mma16(acc[mf][nf], a[mf][0], a[mf][1], a[mf][2], a[mf][3],
                          b[nf][0], b[nf][1]);
        }
    }

    // -----------------------------------------------------------------------
    // Epilogues
    // -----------------------------------------------------------------------
    float* __restrict__ C = D.C;
    const float* __restrict__ bias = D.bias;
    const int ldc = D.ldc;

    if (MODE == EPI_PLAIN) {
#pragma unroll
        for (int nf = 0; nf < 8; ++nf) {
            int col = bn + n0 + nf * 8 + qc * 2;
            if (col >= N) continue;
            float2 bv = *(const float2*)(bias + col);
#pragma unroll
            for (int mf = 0; mf < 2; ++mf) {
                int r = bm + m0 + mf * 16 + qr;
                *(float2*)(C + (size_t)r * ldc + col) =
                    make_float2(acc[mf][nf][0] + bv.x, acc[mf][nf][1] + bv.y);
                *(float2*)(C + (size_t)(r + 8) * ldc + col) =
                    make_float2(acc[mf][nf][2] + bv.x, acc[mf][nf][3] + bv.y);
            }
        }
        return;
    }

    if (MODE == EPI_Q) {
        const int gn0  = bn + n0;
        const int h    = gn0 / QK_HEAD;
        const int w0   = gn0 % QK_HEAD;
        const bool rope = (w0 == 128);

        if (!rope) {
#pragma unroll
            for (int nf = 0; nf < 8; ++nf) {
                int col = gn0 + nf * 8 + qc * 2;
                float2 bv = *(const float2*)(bias + col);
                int oc = w0 + nf * 8 + qc * 2;
#pragma unroll
                for (int mf = 0; mf < 2; ++mf) {
#pragma unroll
                    for (int half = 0; half < 2; ++half) {
                        int r = bm + m0 + mf * 16 + qr + half * 8;
                        int b = r >> 12, s = r & (Ss - 1);
                        float* op = C + (((size_t)(b * NH + h) * Ss + s) * OUT_D) + oc;
                        *(float2*)op = make_float2(acc[mf][nf][half * 2]     + bv.x,
                                                   acc[mf][nf][half * 2 + 1] + bv.y);
                    }
                }
            }
        } else {
#pragma unroll
            for (int nf = 0; nf < 4; ++nf) {
                int d0  = nf * 8 + qc * 2;
                int col1 = gn0 + nf * 8 + qc * 2;
                int col2 = col1 + 32;
                float2 bv1 = *(const float2*)(bias + col1);
                float2 bv2 = *(const float2*)(bias + col2);
#pragma unroll
                for (int mf = 0; mf < 2; ++mf) {
#pragma unroll
                    for (int half = 0; half < 2; ++half) {
                        int r = bm + m0 + mf * 16 + qr + half * 8;
                        int b = r >> 12, s = r & (Ss - 1);
                        float ca = g_cos[s * 32 + d0],      sa = g_sin[s * 32 + d0];
                        float cbq = g_cos[s * 32 + d0 + 1], sbq = g_sin[s * 32 + d0 + 1];
                        float x1a = acc[mf][nf][half * 2]         + bv1.x;
                        float x1b = acc[mf][nf][half * 2 + 1]     + bv1.y;
                        float x2a = acc[mf][nf + 4][half * 2]     + bv2.x;
                        float x2b = acc[mf][nf + 4][half * 2 + 1] + bv2.y;
                        float* op = C + (((size_t)(b * NH + h) * Ss + s) * OUT_D);
                        *(float2*)(op + 128 + d0) =
                            make_float2(x1a * ca - x2a * sa, x1b * cbq - x2b * sbq);
                        *(float2*)(op + 160 + d0) =
                            make_float2(x2a * ca + x1a * sa, x2b * cbq + x1b * sbq);
                    }
                }
            }
        }
        return;
    }

    // MODE == EPI_KV
    {
#pragma unroll
        for (int nf = 0; nf < 8; ++nf) {
            int col = bn + n0 + nf * 8 + qc * 2;
            int h   = col >> 8;
            int cin = col & 255;
            float2 bv = *(const float2*)(bias + col);
            int oc = (cin < 128) ? (192 + cin) : (384 + (cin - 128));
#pragma unroll
            for (int mf = 0; mf < 2; ++mf) {
#pragma unroll
                for (int half = 0; half < 2; ++half) {
                    int r = bm + m0 + mf * 16 + qr + half * 8;
                    int b = r >> 12, s = r & (Ss - 1);
                    float* op = C + (((size_t)(b * NH + h) * Ss + s) * OUT_D) + oc;
                    *(float2*)op = make_float2(acc[mf][nf][half * 2]     + bv.x,
                                               acc[mf][nf][half * 2 + 1] + bv.y);
                }
            }
        }
    }
}

// ---------------------------------------------------------------------------
// Prep kernel: rope table + toHalf(hidden, wqa, wkva), segmented 1D grid.
// ---------------------------------------------------------------------------
namespace {
constexpr int ROPE_BLKS = (Ss * 32) / 256;                   // 512
constexpr int HID_BLKS  = (Mrows * HID / 4) / 2048;          // 2048
constexpr int WQA_BLKS  = (Q_LR * HID / 4) / 2048;           // 192
constexpr int WKVA_BLKS = (KVC_D * HID / 4) / 2048;          // 144
constexpr int PREP_BLKS = ROPE_BLKS + HID_BLKS + WQA_BLKS + WKVA_BLKS;
constexpr int WQB_BLKS  = (QD * Q_LR / 4) / 2048;            // 288
constexpr int WKVB_BLKS = (KVD * KV_LR / 4) / 2048;          // 256
}

__global__ void __launch_bounds__(256) prep_kernel(
    const float4* __restrict__ hidden,
    const float4* __restrict__ wqa,
    const float4* __restrict__ wkva)
{
    int bid = blockIdx.x;
    if (bid < ROPE_BLKS) {
        int idx = bid * 256 + threadIdx.x;
        int dd = idx & 31;
        int s  = idx >> 5;
        float inv_freq = powf(10000.f, -(float)dd * (1.f / 32.f));
        float ang = (float)s * inv_freq;
        float sn, cs;
        sincosf(ang, &sn, &cs);
        g_cos[idx] = cs;
        g_sin[idx] = sn;
        return;
    }
    bid -= ROPE_BLKS;
    if (bid < HID_BLKS) { conv_chunk(hidden, (uint2*)g_hidh, bid); return; }
    bid -= HID_BLKS;
    if (bid < WQA_BLKS) { conv_chunk(wqa, (uint2*)g_wqah, bid); return; }
    bid -= WQA_BLKS;
    conv_chunk(wkva, (uint2*)g_wkvah, bid);
}

// ---------------------------------------------------------------------------
// Fused LN kernel: bid < Mrows -> LN(qc) -> qch; else LN(kvc) -> kvch + krope.
// gamma/beta passed as kernel args (graph-capture safe).
// ---------------------------------------------------------------------------
__global__ void __launch_bounds__(256) ln_fused_kernel(
    const float* __restrict__ gamma_q, const float* __restrict__ beta_q,
    const float* __restrict__ gamma_kv, const float* __restrict__ beta_kv,
    float* __restrict__ out)
{
    const bool isQ = (blockIdx.x < (unsigned)Mrows);
    const int row  = isQ ? blockIdx.x : (blockIdx.x - Mrows);
    const int D    = isQ ? Q_LR : KV_LR;
    const float* x = (isQ ? g_qc : g_kvc) + (size_t)row * (isQ ? Q_LR : KVC_D);
    __half* y      = (isQ ? g_qch : g_kvch) + (size_t)row * (isQ ? Q_LR : KV_LR);
    const float* gamma = isQ ? gamma_q : gamma_kv;
    const float* beta  = isQ ? beta_q  : beta_kv;

    float s = 0.f, s2 = 0.f;
    for (int i = threadIdx.x; i < D; i += 256) {
        float v = x[i];
        s += v; s2 += v * v;
    }
    __shared__ float shs[8], shs2[8];
#pragma unroll
    for (int o = 16; o > 0; o >>= 1) {
        s  += __shfl_down_sync(0xffffffffu, s,  o);
        s2 += __shfl_down_sync(0xffffffffu, s2, o);
    }
    int w = threadIdx.x >> 5, l = threadIdx.x & 31;
    if (l == 0) { shs[w] = s; shs2[w] = s2; }
    __syncthreads();
    if (w == 0) {
        s  = (l < 8) ? shs[l]  : 0.f;
        s2 = (l < 8) ? shs2[l] : 0.f;
#pragma unroll
        for (int o = 4; o > 0; o >>= 1) {
            s  += __shfl_down_sync(0xffffffffu, s,  o);
            s2 += __shfl_down_sync(0xffffffffu, s2, o);
        }
        if (l == 0) { shs[0] = s; shs2[0] = s2; }
    }
    __syncthreads();
    float mu  = shs[0] / D;
    float var = shs2[0] / D - mu * mu;
    float inv = rsqrtf(var + 1e-5f);

    for (int i = threadIdx.x; i < D; i += 256)
        y[i] = __float2half_rn((x[i] - mu) * inv * gamma[i] + beta[i]);

    if (!isQ) {
        // krope: rope(kvc[row, 512:576]) broadcast to 16 heads, cols 320..383
        int t  = threadIdx.x;
        int d  = t & 63;
        int dd = d & 31;
        int h0 = t >> 6;                       // 0..3
        int b  = row >> 12, ss = row & (Ss - 1);
        const float* tail = x + KV_LR;         // kvc row tail
        float x1 = tail[dd], x2 = tail[dd + 32];
        float c = g_cos[ss * 32 + dd], sn = g_sin[ss * 32 + dd];
        float val = (d < 32) ? (x1 * c - x2 * sn) : (x2 * c + x1 * sn);
#pragma unroll
        for (int hh = 0; hh < 4; ++hh) {
            int h = h0 + hh * 4;
            out[(((size_t)(b * NH + h) * Ss + ss) * OUT_D) + 320 + d] = val;
        }
    }
}

// ---------------------------------------------------------------------------
// Launch
// ---------------------------------------------------------------------------
extern "C" void kernel_launch(void* const* d_in, const int* /*in_sizes*/, int /*n_in*/,
                              void* d_out, int /*out_size*/)
{
    const float* hidden   = (const float*)d_in[0];
    const float* w_qa     = (const float*)d_in[1];
    const float* b_qa     = (const float*)d_in[2];
    const float* g_qa_ln  = (const float*)d_in[3];
    const float* b_qa_ln  = (const float*)d_in[4];
    const float* w_qb     = (const float*)d_in[5];
    const float* b_qb     = (const float*)d_in[6];
    const float* w_kva    = (const float*)d_in[7];
    const float* b_kva    = (const float*)d_in[8];
    const float* g_kva_ln = (const float*)d_in[9];
    const float* b_kva_ln = (const float*)d_in[10];
    const float* w_kvb    = (const float*)d_in[11];
    const float* b_kvb    = (const float*)d_in[12];
    float* out = (float*)d_out;

    float  *qc, *kvc;
    __half *qch, *kvch, *hidh, *wqah, *wqbh, *wkvah, *wkvbh;
    cudaGetSymbolAddress((void**)&qc,    g_qc);
    cudaGetSymbolAddress((void**)&kvc,   g_kvc);
    cudaGetSymbolAddress((void**)&qch,   g_qch);
    cudaGetSymbolAddress((void**)&kvch,  g_kvch);
    cudaGetSymbolAddress((void**)&hidh,  g_hidh);
    cudaGetSymbolAddress((void**)&wqah,  g_wqah);
    cudaGetSymbolAddress((void**)&wqbh,  g_wqbh);
    cudaGetSymbolAddress((void**)&wkvah, g_wkvah);
    cudaGetSymbolAddress((void**)&wkvbh, g_wkvbh);

    cudaFuncSetAttribute(gemm_mma_f16_dual,
                         cudaFuncAttributeMaxDynamicSharedMemorySize, GEMM_SMEM);

    // --- prep: rope table + toHalf(hidden, wqa, wkva) ---
    prep_kernel<<<PREP_BLKS, 256>>>((const float4*)hidden,
                                    (const float4*)w_qa, (const float4*)w_kva);

    const int mb = Mrows / BM;   // 64

    // --- fused G1 + G3, with wqb/wkvb conversion filling the partial wave ---
    {
        GemmDesc d0{hidh, HID, wqah,  HID, b_qa,  qc,  Q_LR,  Q_LR,  HID, EPI_PLAIN};
        GemmDesc d1{hidh, HID, wkvah, HID, b_kva, kvc, KVC_D, KVC_D, HID, EPI_PLAIN};
        ConvDesc c0{(const float4*)w_qb,  (uint2*)wqbh,  WQB_BLKS};
        ConvDesc c1{(const float4*)w_kvb, (uint2*)wkvbh, WKVB_BLKS};
        int nb0 = Q_LR / BN;                     // 6
        int nb1 = (KVC_D + BN - 1) / BN;         // 5
        int nbx = nb0 + nb1;                     // 11
        gemm_mma_f16_dual<<<nbx * mb + WQB_BLKS + WKVB_BLKS, 256, GEMM_SMEM>>>(
            d0, d1, nb0, nbx, mb, c0, c1);
    }

    // --- fused LN(qc) + LN(kvc) + krope ---
    ln_fused_kernel<<<2 * Mrows, 256>>>(g_qa_ln, b_qa_ln, g_kva_ln, b_kva_ln, out);

    // --- fused G2 + G4: q (RoPE-fused) and kv (scatter-fused) into out ---
    {
        GemmDesc d0{qch,  Q_LR,  wqbh,  Q_LR,  b_qb,  out, OUT_D, QD,  Q_LR,  EPI_Q};
        GemmDesc d1{kvch, KV_LR, wkvbh, KV_LR, b_kvb, out, OUT_D, KVD, KV_LR, EPI_KV};
        ConvDesc cz{nullptr, nullptr, 0};
        int nb0 = QD / BN;                       // 24
        int nb1 = KVD / BN;                      // 32
        int nbx = nb0 + nb1;                     // 56
        gemm_mma_f16_dual<<<nbx * mb, 256, GEMM_SMEM>>>(
            d0, d1, nb0, nbx, mb, cz, cz);
    }
}

// round 13
// speedup vs baseline: 1.5304x; 1.5304x over previous
#include <cuda_runtime.h>
#include <cuda_fp16.h>
#include <cstdint>
#include <math.h>

// ---------------------------------------------------------------------------
// Problem constants
// ---------------------------------------------------------------------------
namespace {
constexpr int HID     = 2048;
constexpr int QK_NOPE = 128;
constexpr int QK_ROPE = 64;
constexpr int QK_HEAD = QK_NOPE + QK_ROPE;        // 192
constexpr int Q_LR    = 768;
constexpr int KV_LR   = 512;
constexpr int NH      = 16;
constexpr int V_DIM   = 128;
constexpr int Bb      = 2;
constexpr int Ss      = 4096;
constexpr int Mrows   = Bb * Ss;                  // 8192
constexpr int QD      = NH * QK_HEAD;             // 3072
constexpr int KVD     = NH * (QK_NOPE + V_DIM);   // 4096
constexpr int KVC_D   = KV_LR + QK_ROPE;          // 576
constexpr int OUT_D   = 512;
}

// ---------------------------------------------------------------------------
// Device scratch
// ---------------------------------------------------------------------------
__device__ float  g_qc  [Mrows * Q_LR];
__device__ float  g_kvc [Mrows * KVC_D];
__device__ __half g_qch [Mrows * Q_LR];
__device__ __half g_kvch[Mrows * KV_LR];
__device__ __half g_hidh[Mrows * HID];
__device__ __half g_wqah [Q_LR * HID];
__device__ __half g_wqbh [QD * Q_LR];
__device__ __half g_wkvah[KVC_D * HID];
__device__ __half g_wkvbh[KVD * KV_LR];
__device__ float  g_cos [Ss * 32];
__device__ float  g_sin [Ss * 32];

// ---------------------------------------------------------------------------
// Helpers
// ---------------------------------------------------------------------------
__device__ __forceinline__ uint32_t smem_u32(const void* p) {
    uint32_t a;
    asm("{ .reg .u64 t; cvta.to.shared.u64 t, %1; cvt.u32.u64 %0, t; }"
        : "=r"(a) : "l"(p));
    return a;
}

__device__ __forceinline__ void cp_async16(uint32_t dst, const void* src, bool valid) {
    int sz = valid ? 16 : 0;
    asm volatile("cp.async.ca.shared.global [%0], [%1], 16, %2;"
                 :: "r"(dst), "l"(src), "r"(sz) : "memory");
}
__device__ __forceinline__ void cp_commit() {
    asm volatile("cp.async.commit_group;" ::: "memory");
}
template <int N>
__device__ __forceinline__ void cp_wait() {
    asm volatile("cp.async.wait_group %0;" :: "n"(N) : "memory");
}

__device__ __forceinline__ void ldsm4(uint32_t& r0, uint32_t& r1,
                                      uint32_t& r2, uint32_t& r3, uint32_t addr) {
    asm volatile("ldmatrix.sync.aligned.m8n8.x4.shared.b16 {%0,%1,%2,%3}, [%4];"
                 : "=r"(r0), "=r"(r1), "=r"(r2), "=r"(r3) : "r"(addr));
}

__device__ __forceinline__ void mma16(float* c,
                                      uint32_t a0, uint32_t a1, uint32_t a2, uint32_t a3,
                                      uint32_t b0, uint32_t b1) {
    asm volatile(
        "mma.sync.aligned.m16n8k16.row.col.f32.f16.f16.f32 "
        "{%0,%1,%2,%3}, {%4,%5,%6,%7}, {%8,%9}, {%0,%1,%2,%3};"
        : "+f"(c[0]), "+f"(c[1]), "+f"(c[2]), "+f"(c[3])
        : "r"(a0), "r"(a1), "r"(a2), "r"(a3), "r"(b0), "r"(b1));
}

__device__ __forceinline__ void conv_chunk(const float4* __restrict__ src,
                                           uint2* __restrict__ dst, int chunk) {
    int base = chunk * 2048 + threadIdx.x;
#pragma unroll
    for (int j = 0; j < 8; ++j) {
        int idx = base + j * 256;
        float4 v = src[idx];
        __half2 h0 = __floats2half2_rn(v.x, v.y);
        __half2 h1 = __floats2half2_rn(v.z, v.w);
        dst[idx] = make_uint2(*(uint32_t*)&h0, *(uint32_t*)&h1);
    }
}

// ---------------------------------------------------------------------------
// GEMM config: block 128x128x32, 256 threads, 8 warps (4M x 2N), warp tile
// 32x64, 3-stage cp.async, 2 CTAs/SM.  (Exact R9 kernel — conversion work is
// kept OUT of this kernel to avoid register spills.)
// ---------------------------------------------------------------------------
namespace {
constexpr int BM = 128;
constexpr int BN = 128;
constexpr int BK = 32;
constexpr int NSTAGE = 3;
constexpr int LDSH = 40;
constexpr int A_ST_H = BM * LDSH;
constexpr int B_ST_H = BN * LDSH;
constexpr int STAGE_H = A_ST_H + B_ST_H;              // 10240 halves
constexpr uint32_t GEMM_SMEM = NSTAGE * STAGE_H * 2;  // 61440 B
}

enum { EPI_PLAIN = 0, EPI_Q = 1, EPI_KV = 2 };

struct GemmDesc {
    const __half* A;  int lda;
    const __half* B;  int ldb;
    const float*  bias;
    float*        C;  int ldc;
    int N, K, mode;
};

// Two GEMMs fused in one launch: blockIdx.x < split -> d0, else d1.
__global__ void __launch_bounds__(256, 2)
gemm_mma_f16_dual(GemmDesc d0, GemmDesc d1, int split)
{
    extern __shared__ __half smh[];
    const uint32_t sm_b = smem_u32(smh);

    const GemmDesc& D = (blockIdx.x < (unsigned)split) ? d0 : d1;
    const int bn = ((blockIdx.x < (unsigned)split) ? blockIdx.x
                                                   : (blockIdx.x - split)) * BN;
    const __half* __restrict__ A = D.A;
    const __half* __restrict__ B = D.B;
    const int lda = D.lda, ldb = D.ldb, N = D.N, K = D.K, MODE = D.mode;

    const int tid  = threadIdx.x;
    const int wid  = tid >> 5;
    const int lane = tid & 31;
    const int wm   = wid & 3;
    const int wn   = wid >> 2;
    const int bm   = blockIdx.y * BM;
    const int m0   = wm * 32;
    const int n0   = wn * 64;
    const int qr   = lane >> 2;
    const int qc   = lane & 3;

    const int aRow  = m0 + (lane & 15);
    const int aKoff = (lane >> 4) * 8;
    const int bRow  = n0 + ((lane >> 4) & 1) * 8 + (lane & 7);
    const int bKoff = ((lane >> 3) & 1) * 8;

    float acc[2][8][4];
#pragma unroll
    for (int i = 0; i < 2; i++)
#pragma unroll
        for (int j = 0; j < 8; j++)
#pragma unroll
            for (int k = 0; k < 4; k++) acc[i][j][k] = 0.f;

    const int T = K / BK;

    auto issue_stage = [&](int t) {
        const int buf = t % NSTAGE;
        const uint32_t aBase = sm_b + (uint32_t)buf * STAGE_H * 2;
        const uint32_t bBase = aBase + A_ST_H * 2;
        const int k0 = t * BK;
#pragma unroll
        for (int j = 0; j < 2; ++j) {
            int i = j * 256 + tid;
            int r = i >> 2, c8 = i & 3;
            cp_async16(aBase + (uint32_t)(r * LDSH * 2 + c8 * 16),
                       A + (size_t)(bm + r) * lda + k0 + c8 * 8, true);
        }
#pragma unroll
        for (int j = 0; j < 2; ++j) {
            int i = j * 256 + tid;
            int r = i >> 2, c8 = i & 3;
            int n = bn + r;
            cp_async16(bBase + (uint32_t)(r * LDSH * 2 + c8 * 16),
                       B + (size_t)(n < N ? n : 0) * ldb + k0 + c8 * 8, n < N);
        }
        cp_commit();
    };

#pragma unroll
    for (int i = 0; i < NSTAGE - 1; ++i)
        if (i < T) issue_stage(i);

    for (int t = 0; t < T; ++t) {
        if (t < T - 1) cp_wait<NSTAGE - 2>(); else cp_wait<0>();
        __syncthreads();
        if (t + NSTAGE - 1 < T) issue_stage(t + NSTAGE - 1);

        const uint32_t As_u = sm_b + (uint32_t)(t % NSTAGE) * STAGE_H * 2;
        const uint32_t Bs_u = As_u + A_ST_H * 2;

#pragma unroll
        for (int kk = 0; kk < 2; ++kk) {
            const int kb = kk * 16;
            uint32_t a[2][4];
#pragma unroll
            for (int mf = 0; mf < 2; ++mf)
                ldsm4(a[mf][0], a[mf][1], a[mf][2], a[mf][3],
                      As_u + (uint32_t)((aRow + mf * 16) * LDSH + kb + aKoff) * 2);
            uint32_t b[8][2];
#pragma unroll
            for (int nfp = 0; nfp < 4; ++nfp)
                ldsm4(b[2 * nfp][0], b[2 * nfp][1], b[2 * nfp + 1][0], b[2 * nfp + 1][1],
                      Bs_u + (uint32_t)((bRow + nfp * 16) * LDSH + kb + bKoff) * 2);
#pragma unroll
            for (int nf = 0; nf < 8; ++nf)
#pragma unroll
                for (int mf = 0; mf < 2; ++mf)
                    mma16(acc[mf][nf], a[mf][0], a[mf][1], a[mf][2], a[mf][3],
                          b[nf][0], b[nf][1]);
        }
    }

    // -----------------------------------------------------------------------
    // Epilogues
    // -----------------------------------------------------------------------
    float* __restrict__ C = D.C;
    const float* __restrict__ bias = D.bias;
    const int ldc = D.ldc;

    if (MODE == EPI_PLAIN) {
#pragma unroll
        for (int nf = 0; nf < 8; ++nf) {
            int col = bn + n0 + nf * 8 + qc * 2;
            if (col >= N) continue;
            float2 bv = *(const float2*)(bias + col);
#pragma unroll
            for (int mf = 0; mf < 2; ++mf) {
                int r = bm + m0 + mf * 16 + qr;
                *(float2*)(C + (size_t)r * ldc + col) =
                    make_float2(acc[mf][nf][0] + bv.x, acc[mf][nf][1] + bv.y);
                *(float2*)(C + (size_t)(r + 8) * ldc + col) =
                    make_float2(acc[mf][nf][2] + bv.x, acc[mf][nf][3] + bv.y);
            }
        }
        return;
    }

    if (MODE == EPI_Q) {
        const int gn0  = bn + n0;
        const int h    = gn0 / QK_HEAD;
        const int w0   = gn0 % QK_HEAD;
        const bool rope = (w0 == 128);

        if (!rope) {
#pragma unroll
            for (int nf = 0; nf < 8; ++nf) {
                int col = gn0 + nf * 8 + qc * 2;
                float2 bv = *(const float2*)(bias + col);
                int oc = w0 + nf * 8 + qc * 2;
#pragma unroll
                for (int mf = 0; mf < 2; ++mf) {
#pragma unroll
                    for (int half = 0; half < 2; ++half) {
                        int r = bm + m0 + mf * 16 + qr + half * 8;
                        int b = r >> 12, s = r & (Ss - 1);
                        float* op = C + (((size_t)(b * NH + h) * Ss + s) * OUT_D) + oc;
                        *(float2*)op = make_float2(acc[mf][nf][half * 2]     + bv.x,
                                                   acc[mf][nf][half * 2 + 1] + bv.y);
                    }
                }
            }
        } else {
#pragma unroll
            for (int nf = 0; nf < 4; ++nf) {
                int d0  = nf * 8 + qc * 2;
                int col1 = gn0 + nf * 8 + qc * 2;
                int col2 = col1 + 32;
                float2 bv1 = *(const float2*)(bias + col1);
                float2 bv2 = *(const float2*)(bias + col2);
#pragma unroll
                for (int mf = 0; mf < 2; ++mf) {
#pragma unroll
                    for (int half = 0; half < 2; ++half) {
                        int r = bm + m0 + mf * 16 + qr + half * 8;
                        int b = r >> 12, s = r & (Ss - 1);
                        float ca = g_cos[s * 32 + d0],      sa = g_sin[s * 32 + d0];
                        float cbq = g_cos[s * 32 + d0 + 1], sbq = g_sin[s * 32 + d0 + 1];
                        float x1a = acc[mf][nf][half * 2]         + bv1.x;
                        float x1b = acc[mf][nf][half * 2 + 1]     + bv1.y;
                        float x2a = acc[mf][nf + 4][half * 2]     + bv2.x;
                        float x2b = acc[mf][nf + 4][half * 2 + 1] + bv2.y;
                        float* op = C + (((size_t)(b * NH + h) * Ss + s) * OUT_D);
                        *(float2*)(op + 128 + d0) =
                            make_float2(x1a * ca - x2a * sa, x1b * cbq - x2b * sbq);
                        *(float2*)(op + 160 + d0) =
                            make_float2(x2a * ca + x1a * sa, x2b * cbq + x1b * sbq);
                    }
                }
            }
        }
        return;
    }

    // MODE == EPI_KV
    {
#pragma unroll
        for (int nf = 0; nf < 8; ++nf) {
            int col = bn + n0 + nf * 8 + qc * 2;
            int h   = col >> 8;
            int cin = col & 255;
            float2 bv = *(const float2*)(bias + col);
            int oc = (cin < 128) ? (192 + cin) : (384 + (cin - 128));
#pragma unroll
            for (int mf = 0; mf < 2; ++mf) {
#pragma unroll
                for (int half = 0; half < 2; ++half) {
                    int r = bm + m0 + mf * 16 + qr + half * 8;
                    int b = r >> 12, s = r & (Ss - 1);
                    float* op = C + (((size_t)(b * NH + h) * Ss + s) * OUT_D) + oc;
                    *(float2*)op = make_float2(acc[mf][nf][half * 2]     + bv.x,
                                               acc[mf][nf][half * 2 + 1] + bv.y);
                }
            }
        }
    }
}

// ---------------------------------------------------------------------------
// Prep kernel: rope table + ALL fp16 conversions (hidden + 4 weights).
// One chunk (2048 float4 = 8192 floats) per block, one block per chunk.
// ---------------------------------------------------------------------------
namespace {
constexpr int ROPE_BLKS = (Ss * 32) / 256;                   // 512
constexpr int HID_BLKS  = (Mrows * HID / 4) / 2048;          // 2048
constexpr int WQA_BLKS  = (Q_LR * HID / 4) / 2048;           // 192
constexpr int WKVA_BLKS = (KVC_D * HID / 4) / 2048;          // 144
constexpr int WQB_BLKS  = (QD * Q_LR / 4) / 2048;            // 288
constexpr int WKVB_BLKS = (KVD * KV_LR / 4) / 2048;          // 256
constexpr int PREP_BLKS = ROPE_BLKS + HID_BLKS + WQA_BLKS + WKVA_BLKS
                        + WQB_BLKS + WKVB_BLKS;
static_assert((Mrows * HID / 4) % 2048 == 0, "hid chunks");
static_assert((Q_LR * HID / 4) % 2048 == 0, "wqa chunks");
static_assert((KVC_D * HID / 4) % 2048 == 0, "wkva chunks");
static_assert((QD * Q_LR / 4) % 2048 == 0, "wqb chunks");
static_assert((KVD * KV_LR / 4) % 2048 == 0, "wkvb chunks");
}

__global__ void __launch_bounds__(256) prep_kernel(
    const float4* __restrict__ hidden,
    const float4* __restrict__ wqa,
    const float4* __restrict__ wkva,
    const float4* __restrict__ wqb,
    const float4* __restrict__ wkvb)
{
    int bid = blockIdx.x;
    if (bid < ROPE_BLKS) {
        int idx = bid * 256 + threadIdx.x;
        int dd = idx & 31;
        int s  = idx >> 5;
        float inv_freq = powf(10000.f, -(float)dd * (1.f / 32.f));
        float ang = (float)s * inv_freq;
        float sn, cs;
        sincosf(ang, &sn, &cs);
        g_cos[idx] = cs;
        g_sin[idx] = sn;
        return;
    }
    bid -= ROPE_BLKS;
    if (bid < HID_BLKS)  { conv_chunk(hidden, (uint2*)g_hidh, bid); return; }
    bid -= HID_BLKS;
    if (bid < WQA_BLKS)  { conv_chunk(wqa,  (uint2*)g_wqah,  bid); return; }
    bid -= WQA_BLKS;
    if (bid < WKVA_BLKS) { conv_chunk(wkva, (uint2*)g_wkvah, bid); return; }
    bid -= WKVA_BLKS;
    if (bid < WQB_BLKS)  { conv_chunk(wqb,  (uint2*)g_wqbh,  bid); return; }
    bid -= WQB_BLKS;
    conv_chunk(wkvb, (uint2*)g_wkvbh, bid);
}

// ---------------------------------------------------------------------------
// Fused LN kernel: bid < Mrows -> LN(qc) -> qch; else LN(kvc) -> kvch + krope.
// gamma/beta passed as kernel args (graph-capture safe).
// ---------------------------------------------------------------------------
__global__ void __launch_bounds__(256) ln_fused_kernel(
    const float* __restrict__ gamma_q, const float* __restrict__ beta_q,
    const float* __restrict__ gamma_kv, const float* __restrict__ beta_kv,
    float* __restrict__ out)
{
    const bool isQ = (blockIdx.x < (unsigned)Mrows);
    const int row  = isQ ? blockIdx.x : (blockIdx.x - Mrows);
    const int D    = isQ ? Q_LR : KV_LR;
    const float* x = (isQ ? g_qc : g_kvc) + (size_t)row * (isQ ? Q_LR : KVC_D);
    __half* y      = (isQ ? g_qch : g_kvch) + (size_t)row * (isQ ? Q_LR : KV_LR);
    const float* gamma = isQ ? gamma_q : gamma_kv;
    const float* beta  = isQ ? beta_q  : beta_kv;

    float s = 0.f, s2 = 0.f;
    for (int i = threadIdx.x; i < D; i += 256) {
        float v = x[i];
        s += v; s2 += v * v;
    }
    __shared__ float shs[8], shs2[8];
#pragma unroll
    for (int o = 16; o > 0; o >>= 1) {
        s  += __shfl_down_sync(0xffffffffu, s,  o);
        s2 += __shfl_down_sync(0xffffffffu, s2, o);
    }
    int w = threadIdx.x >> 5, l = threadIdx.x & 31;
    if (l == 0) { shs[w] = s; shs2[w] = s2; }
    __syncthreads();
    if (w == 0) {
        s  = (l < 8) ? shs[l]  : 0.f;
        s2 = (l < 8) ? shs2[l] : 0.f;
#pragma unroll
        for (int o = 4; o > 0; o >>= 1) {
            s  += __shfl_down_sync(0xffffffffu, s,  o);
            s2 += __shfl_down_sync(0xffffffffu, s2, o);
        }
        if (l == 0) { shs[0] = s; shs2[0] = s2; }
    }
    __syncthreads();
    float mu  = shs[0] / D;
    float var = shs2[0] / D - mu * mu;
    float inv = rsqrtf(var + 1e-5f);

    for (int i = threadIdx.x; i < D; i += 256)
        y[i] = __float2half_rn((x[i] - mu) * inv * gamma[i] + beta[i]);

    if (!isQ) {
        // krope: rope(kvc[row, 512:576]) broadcast to 16 heads, cols 320..383
        int t  = threadIdx.x;
        int d  = t & 63;
        int dd = d & 31;
        int h0 = t >> 6;                       // 0..3
        int b  = row >> 12, ss = row & (Ss - 1);
        const float* tail = x + KV_LR;
        float x1 = tail[dd], x2 = tail[dd + 32];
        float c = g_cos[ss * 32 + dd], sn = g_sin[ss * 32 + dd];
        float val = (d < 32) ? (x1 * c - x2 * sn) : (x2 * c + x1 * sn);
#pragma unroll
        for (int hh = 0; hh < 4; ++hh) {
            int h = h0 + hh * 4;
            out[(((size_t)(b * NH + h) * Ss + ss) * OUT_D) + 320 + d] = val;
        }
    }
}

// ---------------------------------------------------------------------------
// Launch
// ---------------------------------------------------------------------------
extern "C" void kernel_launch(void* const* d_in, const int* /*in_sizes*/, int /*n_in*/,
                              void* d_out, int /*out_size*/)
{
    const float* hidden   = (const float*)d_in[0];
    const float* w_qa     = (const float*)d_in[1];
    const float* b_qa     = (const float*)d_in[2];
    const float* g_qa_ln  = (const float*)d_in[3];
    const float* b_qa_ln  = (const float*)d_in[4];
    const float* w_qb     = (const float*)d_in[5];
    const float* b_qb     = (const float*)d_in[6];
    const float* w_kva    = (const float*)d_in[7];
    const float* b_kva    = (const float*)d_in[8];
    const float* g_kva_ln = (const float*)d_in[9];
    const float* b_kva_ln = (const float*)d_in[10];
    const float* w_kvb    = (const float*)d_in[11];
    const float* b_kvb    = (const float*)d_in[12];
    float* out = (float*)d_out;

    float  *qc, *kvc;
    __half *qch, *kvch, *hidh, *wqah, *wqbh, *wkvah, *wkvbh;
    cudaGetSymbolAddress((void**)&qc,    g_qc);
    cudaGetSymbolAddress((void**)&kvc,   g_kvc);
    cudaGetSymbolAddress((void**)&qch,   g_qch);
    cudaGetSymbolAddress((void**)&kvch,  g_kvch);
    cudaGetSymbolAddress((void**)&hidh,  g_hidh);
    cudaGetSymbolAddress((void**)&wqah,  g_wqah);
    cudaGetSymbolAddress((void**)&wqbh,  g_wqbh);
    cudaGetSymbolAddress((void**)&wkvah, g_wkvah);
    cudaGetSymbolAddress((void**)&wkvbh, g_wkvbh);

    cudaFuncSetAttribute(gemm_mma_f16_dual,
                         cudaFuncAttributeMaxDynamicSharedMemorySize, GEMM_SMEM);

    // --- prep: rope table + all fp16 conversions, one launch ---
    prep_kernel<<<PREP_BLKS, 256>>>((const float4*)hidden,
                                    (const float4*)w_qa, (const float4*)w_kva,
                                    (const float4*)w_qb, (const float4*)w_kvb);

    const int mb = Mrows / BM;   // 64

    // --- fused G1 + G3: q_c and kv_c from hidden ---
    {
        GemmDesc d0{hidh, HID, wqah,  HID, b_qa,  qc,  Q_LR,  Q_LR,  HID, EPI_PLAIN};
        GemmDesc d1{hidh, HID, wkvah, HID, b_kva, kvc, KVC_D, KVC_D, HID, EPI_PLAIN};
        int nb0 = Q_LR / BN;                     // 6
        int nb1 = (KVC_D + BN - 1) / BN;         // 5
        gemm_mma_f16_dual<<<dim3(nb0 + nb1, mb), 256, GEMM_SMEM>>>(d0, d1, nb0);
    }

    // --- fused LN(qc) + LN(kvc) + krope ---
    ln_fused_kernel<<<2 * Mrows, 256>>>(g_qa_ln, b_qa_ln, g_kva_ln, b_kva_ln, out);

    // --- fused G2 + G4: q (RoPE-fused) and kv (scatter-fused) into out ---
    {
        GemmDesc d0{qch,  Q_LR,  wqbh,  Q_LR,  b_qb,  out, OUT_D, QD,  Q_LR,  EPI_Q};
        GemmDesc d1{kvch, KV_LR, wkvbh, KV_LR, b_kvb, out, OUT_D, KVD, KV_LR, EPI_KV};
        int nb0 = QD / BN;                       // 24
        int nb1 = KVD / BN;                      // 32
        gemm_mma_f16_dual<<<dim3(nb0 + nb1, mb), 256, GEMM_SMEM>>>(d0, d1, nb0);
    }
}

// round 14
// speedup vs baseline: 1.5497x; 1.0127x over previous
#include <cuda_runtime.h>
#include <cuda_fp16.h>
#include <cstdint>
#include <math.h>

// ---------------------------------------------------------------------------
// Problem constants
// ---------------------------------------------------------------------------
namespace {
constexpr int HID     = 2048;
constexpr int QK_NOPE = 128;
constexpr int QK_ROPE = 64;
constexpr int QK_HEAD = QK_NOPE + QK_ROPE;        // 192
constexpr int Q_LR    = 768;
constexpr int KV_LR   = 512;
constexpr int NH      = 16;
constexpr int V_DIM   = 128;
constexpr int Bb      = 2;
constexpr int Ss      = 4096;
constexpr int Mrows   = Bb * Ss;                  // 8192
constexpr int QD      = NH * QK_HEAD;             // 3072
constexpr int KVD     = NH * (QK_NOPE + V_DIM);   // 4096
constexpr int KVC_D   = KV_LR + QK_ROPE;          // 576
constexpr int OUT_D   = 512;
}

// ---------------------------------------------------------------------------
// Device scratch
// ---------------------------------------------------------------------------
__device__ float  g_qc  [Mrows * Q_LR];
__device__ float  g_kvc [Mrows * KVC_D];
__device__ __half g_qch [Mrows * Q_LR];
__device__ __half g_kvch[Mrows * KV_LR];
__device__ __half g_hidh[Mrows * HID];
__device__ __half g_wqah [Q_LR * HID];
__device__ __half g_wqbh [QD * Q_LR];
__device__ __half g_wkvah[KVC_D * HID];
__device__ __half g_wkvbh[KVD * KV_LR];
__device__ float  g_cos [Ss * 32];
__device__ float  g_sin [Ss * 32];

// ---------------------------------------------------------------------------
// Helpers
// ---------------------------------------------------------------------------
__device__ __forceinline__ uint32_t smem_u32(const void* p) {
    uint32_t a;
    asm("{ .reg .u64 t; cvta.to.shared.u64 t, %1; cvt.u32.u64 %0, t; }"
        : "=r"(a) : "l"(p));
    return a;
}

__device__ __forceinline__ void cp_async16(uint32_t dst, const void* src, bool valid) {
    int sz = valid ? 16 : 0;
    asm volatile("cp.async.ca.shared.global [%0], [%1], 16, %2;"
                 :: "r"(dst), "l"(src), "r"(sz) : "memory");
}
__device__ __forceinline__ void cp_commit() {
    asm volatile("cp.async.commit_group;" ::: "memory");
}
template <int N>
__device__ __forceinline__ void cp_wait() {
    asm volatile("cp.async.wait_group %0;" :: "n"(N) : "memory");
}

__device__ __forceinline__ void ldsm4(uint32_t& r0, uint32_t& r1,
                                      uint32_t& r2, uint32_t& r3, uint32_t addr) {
    asm volatile("ldmatrix.sync.aligned.m8n8.x4.shared.b16 {%0,%1,%2,%3}, [%4];"
                 : "=r"(r0), "=r"(r1), "=r"(r2), "=r"(r3) : "r"(addr));
}

__device__ __forceinline__ void mma16(float* c,
                                      uint32_t a0, uint32_t a1, uint32_t a2, uint32_t a3,
                                      uint32_t b0, uint32_t b1) {
    asm volatile(
        "mma.sync.aligned.m16n8k16.row.col.f32.f16.f16.f32 "
        "{%0,%1,%2,%3}, {%4,%5,%6,%7}, {%8,%9}, {%0,%1,%2,%3};"
        : "+f"(c[0]), "+f"(c[1]), "+f"(c[2]), "+f"(c[3])
        : "r"(a0), "r"(a1), "r"(a2), "r"(a3), "r"(b0), "r"(b1));
}

__device__ __forceinline__ void conv_chunk(const float4* __restrict__ src,
                                           uint2* __restrict__ dst, int chunk) {
    int base = chunk * 2048 + threadIdx.x;
#pragma unroll
    for (int j = 0; j < 8; ++j) {
        int idx = base + j * 256;
        float4 v = src[idx];
        __half2 h0 = __floats2half2_rn(v.x, v.y);
        __half2 h1 = __floats2half2_rn(v.z, v.w);
        dst[idx] = make_uint2(*(uint32_t*)&h0, *(uint32_t*)&h1);
    }
}

// ---------------------------------------------------------------------------
// GEMM config: block 128x128x64, 256 threads, 8 warps (4M x 2N), warp tile
// 32x64, 3-stage cp.async, 2 CTAs/SM.
// BK=64 (kk-unroll 4): half the syncs per CTA, 4 independent ldsm/mma groups
// per iter for ILP.  LDSH=72 halves -> 144B row stride: cp.async writes are
// 128B-contiguous per row (coalesced wavefronts); ldmatrix banks (4r+c)%32
// conflict-free; 16B alignment holds (144 = 9*16).
// ---------------------------------------------------------------------------
namespace {
constexpr int BM = 128;
constexpr int BN = 128;
constexpr int BK = 64;                                // halves per K-iter
constexpr int NSTAGE = 3;
constexpr int LDSH = 72;                              // halves/row incl pad
constexpr int A_ST_H = BM * LDSH;                     // 9216 halves
constexpr int B_ST_H = BN * LDSH;                     // 9216 halves
constexpr int STAGE_H = A_ST_H + B_ST_H;              // 18432 halves
constexpr uint32_t GEMM_SMEM = NSTAGE * STAGE_H * 2;  // 110592 B
}

enum { EPI_PLAIN = 0, EPI_Q = 1, EPI_KV = 2 };

struct GemmDesc {
    const __half* A;  int lda;
    const __half* B;  int ldb;
    const float*  bias;
    float*        C;  int ldc;
    int N, K, mode;
};

// Two GEMMs fused in one launch: blockIdx.x < split -> d0, else d1.
__global__ void __launch_bounds__(256, 2)
gemm_mma_f16_dual(GemmDesc d0, GemmDesc d1, int split)
{
    extern __shared__ __half smh[];
    const uint32_t sm_b = smem_u32(smh);

    const GemmDesc& D = (blockIdx.x < (unsigned)split) ? d0 : d1;
    const int bn = ((blockIdx.x < (unsigned)split) ? blockIdx.x
                                                   : (blockIdx.x - split)) * BN;
    const __half* __restrict__ A = D.A;
    const __half* __restrict__ B = D.B;
    const int lda = D.lda, ldb = D.ldb, N = D.N, K = D.K, MODE = D.mode;

    const int tid  = threadIdx.x;
    const int wid  = tid >> 5;
    const int lane = tid & 31;
    const int wm   = wid & 3;
    const int wn   = wid >> 2;
    const int bm   = blockIdx.y * BM;
    const int m0   = wm * 32;
    const int n0   = wn * 64;
    const int qr   = lane >> 2;
    const int qc   = lane & 3;

    const int aRow  = m0 + (lane & 15);
    const int aKoff = (lane >> 4) * 8;
    const int bRow  = n0 + ((lane >> 4) & 1) * 8 + (lane & 7);
    const int bKoff = ((lane >> 3) & 1) * 8;

    float acc[2][8][4];
#pragma unroll
    for (int i = 0; i < 2; i++)
#pragma unroll
        for (int j = 0; j < 8; j++)
#pragma unroll
            for (int k = 0; k < 4; k++) acc[i][j][k] = 0.f;

    const int T = K / BK;

    auto issue_stage = [&](int t) {
        const int buf = t % NSTAGE;
        const uint32_t aBase = sm_b + (uint32_t)buf * STAGE_H * 2;
        const uint32_t bBase = aBase + A_ST_H * 2;
        const int k0 = t * BK;
        // A: 128 rows x 64 halves = 128B/row = 8 chunks of 16B -> 1024 chunks
#pragma unroll
        for (int j = 0; j < 4; ++j) {
            int i = j * 256 + tid;
            int r = i >> 3, c8 = i & 7;
            cp_async16(aBase + (uint32_t)(r * LDSH * 2 + c8 * 16),
                       A + (size_t)(bm + r) * lda + k0 + c8 * 8, true);
        }
#pragma unroll
        for (int j = 0; j < 4; ++j) {
            int i = j * 256 + tid;
            int r = i >> 3, c8 = i & 7;
            int n = bn + r;
            cp_async16(bBase + (uint32_t)(r * LDSH * 2 + c8 * 16),
                       B + (size_t)(n < N ? n : 0) * ldb + k0 + c8 * 8, n < N);
        }
        cp_commit();
    };

#pragma unroll
    for (int i = 0; i < NSTAGE - 1; ++i)
        if (i < T) issue_stage(i);

    for (int t = 0; t < T; ++t) {
        if (t < T - 1) cp_wait<NSTAGE - 2>(); else cp_wait<0>();
        __syncthreads();
        if (t + NSTAGE - 1 < T) issue_stage(t + NSTAGE - 1);

        const uint32_t As_u = sm_b + (uint32_t)(t % NSTAGE) * STAGE_H * 2;
        const uint32_t Bs_u = As_u + A_ST_H * 2;

#pragma unroll
        for (int kk = 0; kk < 4; ++kk) {
            const int kb = kk * 16;
            uint32_t a[2][4];
#pragma unroll
            for (int mf = 0; mf < 2; ++mf)
                ldsm4(a[mf][0], a[mf][1], a[mf][2], a[mf][3],
                      As_u + (uint32_t)((aRow + mf * 16) * LDSH + kb + aKoff) * 2);
            uint32_t b[8][2];
#pragma unroll
            for (int nfp = 0; nfp < 4; ++nfp)
                ldsm4(b[2 * nfp][0], b[2 * nfp][1], b[2 * nfp + 1][0], b[2 * nfp + 1][1],
                      Bs_u + (uint32_t)((bRow + nfp * 16) * LDSH + kb + bKoff) * 2);
#pragma unroll
            for (int nf = 0; nf < 8; ++nf)
#pragma unroll
                for (int mf = 0; mf < 2; ++mf)
                    mma16(acc[mf][nf], a[mf][0], a[mf][1], a[mf][2], a[mf][3],
                          b[nf][0], b[nf][1]);
        }
    }

    // -----------------------------------------------------------------------
    // Epilogues
    // -----------------------------------------------------------------------
    float* __restrict__ C = D.C;
    const float* __restrict__ bias = D.bias;
    const int ldc = D.ldc;

    if (MODE == EPI_PLAIN) {
#pragma unroll
        for (int nf = 0; nf < 8; ++nf) {
            int col = bn + n0 + nf * 8 + qc * 2;
            if (col >= N) continue;
            float2 bv = *(const float2*)(bias + col);
#pragma unroll
            for (int mf = 0; mf < 2; ++mf) {
                int r = bm + m0 + mf * 16 + qr;
                *(float2*)(C + (size_t)r * ldc + col) =
                    make_float2(acc[mf][nf][0] + bv.x, acc[mf][nf][1] + bv.y);
                *(float2*)(C + (size_t)(r + 8) * ldc + col) =
                    make_float2(acc[mf][nf][2] + bv.x, acc[mf][nf][3] + bv.y);
            }
        }
        return;
    }

    if (MODE == EPI_Q) {
        const int gn0  = bn + n0;
        const int h    = gn0 / QK_HEAD;
        const int w0   = gn0 % QK_HEAD;
        const bool rope = (w0 == 128);

        if (!rope) {
#pragma unroll
            for (int nf = 0; nf < 8; ++nf) {
                int col = gn0 + nf * 8 + qc * 2;
                float2 bv = *(const float2*)(bias + col);
                int oc = w0 + nf * 8 + qc * 2;
#pragma unroll
                for (int mf = 0; mf < 2; ++mf) {
#pragma unroll
                    for (int half = 0; half < 2; ++half) {
                        int r = bm + m0 + mf * 16 + qr + half * 8;
                        int b = r >> 12, s = r & (Ss - 1);
                        float* op = C + (((size_t)(b * NH + h) * Ss + s) * OUT_D) + oc;
                        *(float2*)op = make_float2(acc[mf][nf][half * 2]     + bv.x,
                                                   acc[mf][nf][half * 2 + 1] + bv.y);
                    }
                }
            }
        } else {
#pragma unroll
            for (int nf = 0; nf < 4; ++nf) {
                int d0  = nf * 8 + qc * 2;
                int col1 = gn0 + nf * 8 + qc * 2;
                int col2 = col1 + 32;
                float2 bv1 = *(const float2*)(bias + col1);
                float2 bv2 = *(const float2*)(bias + col2);
#pragma unroll
                for (int mf = 0; mf < 2; ++mf) {
#pragma unroll
                    for (int half = 0; half < 2; ++half) {
                        int r = bm + m0 + mf * 16 + qr + half * 8;
                        int b = r >> 12, s = r & (Ss - 1);
                        float ca = g_cos[s * 32 + d0],      sa = g_sin[s * 32 + d0];
                        float cbq = g_cos[s * 32 + d0 + 1], sbq = g_sin[s * 32 + d0 + 1];
                        float x1a = acc[mf][nf][half * 2]         + bv1.x;
                        float x1b = acc[mf][nf][half * 2 + 1]     + bv1.y;
                        float x2a = acc[mf][nf + 4][half * 2]     + bv2.x;
                        float x2b = acc[mf][nf + 4][half * 2 + 1] + bv2.y;
                        float* op = C + (((size_t)(b * NH + h) * Ss + s) * OUT_D);
                        *(float2*)(op + 128 + d0) =
                            make_float2(x1a * ca - x2a * sa, x1b * cbq - x2b * sbq);
                        *(float2*)(op + 160 + d0) =
                            make_float2(x2a * ca + x1a * sa, x2b * cbq + x1b * sbq);
                    }
                }
            }
        }
        return;
    }

    // MODE == EPI_KV
    {
#pragma unroll
        for (int nf = 0; nf < 8; ++nf) {
            int col = bn + n0 + nf * 8 + qc * 2;
            int h   = col >> 8;
            int cin = col & 255;
            float2 bv = *(const float2*)(bias + col);
            int oc = (cin < 128) ? (192 + cin) : (384 + (cin - 128));
#pragma unroll
            for (int mf = 0; mf < 2; ++mf) {
#pragma unroll
                for (int half = 0; half < 2; ++half) {
                    int r = bm + m0 + mf * 16 + qr + half * 8;
                    int b = r >> 12, s = r & (Ss - 1);
                    float* op = C + (((size_t)(b * NH + h) * Ss + s) * OUT_D) + oc;
                    *(float2*)op = make_float2(acc[mf][nf][half * 2]     + bv.x,
                                               acc[mf][nf][half * 2 + 1] + bv.y);
                }
            }
        }
    }
}

// ---------------------------------------------------------------------------
// Prep kernel: rope table + ALL fp16 conversions (hidden + 4 weights).
// ---------------------------------------------------------------------------
namespace {
constexpr int ROPE_BLKS = (Ss * 32) / 256;                   // 512
constexpr int HID_BLKS  = (Mrows * HID / 4) / 2048;          // 2048
constexpr int WQA_BLKS  = (Q_LR * HID / 4) / 2048;           // 192
constexpr int WKVA_BLKS = (KVC_D * HID / 4) / 2048;          // 144
constexpr int WQB_BLKS  = (QD * Q_LR / 4) / 2048;            // 288
constexpr int WKVB_BLKS = (KVD * KV_LR / 4) / 2048;          // 256
constexpr int PREP_BLKS = ROPE_BLKS + HID_BLKS + WQA_BLKS + WKVA_BLKS
                        + WQB_BLKS + WKVB_BLKS;
static_assert((Mrows * HID / 4) % 2048 == 0, "hid chunks");
static_assert((Q_LR * HID / 4) % 2048 == 0, "wqa chunks");
static_assert((KVC_D * HID / 4) % 2048 == 0, "wkva chunks");
static_assert((QD * Q_LR / 4) % 2048 == 0, "wqb chunks");
static_assert((KVD * KV_LR / 4) % 2048 == 0, "wkvb chunks");
}

__global__ void __launch_bounds__(256) prep_kernel(
    const float4* __restrict__ hidden,
    const float4* __restrict__ wqa,
    const float4* __restrict__ wkva,
    const float4* __restrict__ wqb,
    const float4* __restrict__ wkvb)
{
    int bid = blockIdx.x;
    if (bid < ROPE_BLKS) {
        int idx = bid * 256 + threadIdx.x;
        int dd = idx & 31;
        int s  = idx >> 5;
        float inv_freq = powf(10000.f, -(float)dd * (1.f / 32.f));
        float ang = (float)s * inv_freq;
        float sn, cs;
        sincosf(ang, &sn, &cs);
        g_cos[idx] = cs;
        g_sin[idx] = sn;
        return;
    }
    bid -= ROPE_BLKS;
    if (bid < HID_BLKS)  { conv_chunk(hidden, (uint2*)g_hidh, bid); return; }
    bid -= HID_BLKS;
    if (bid < WQA_BLKS)  { conv_chunk(wqa,  (uint2*)g_wqah,  bid); return; }
    bid -= WQA_BLKS;
    if (bid < WKVA_BLKS) { conv_chunk(wkva, (uint2*)g_wkvah, bid); return; }
    bid -= WKVA_BLKS;
    if (bid < WQB_BLKS)  { conv_chunk(wqb,  (uint2*)g_wqbh,  bid); return; }
    bid -= WQB_BLKS;
    conv_chunk(wkvb, (uint2*)g_wkvbh, bid);
}

// ---------------------------------------------------------------------------
// Fused LN kernel: bid < Mrows -> LN(qc) -> qch; else LN(kvc) -> kvch + krope.
// ---------------------------------------------------------------------------
__global__ void __launch_bounds__(256) ln_fused_kernel(
    const float* __restrict__ gamma_q, const float* __restrict__ beta_q,
    const float* __restrict__ gamma_kv, const float* __restrict__ beta_kv,
    float* __restrict__ out)
{
    const bool isQ = (blockIdx.x < (unsigned)Mrows);
    const int row  = isQ ? blockIdx.x : (blockIdx.x - Mrows);
    const int D    = isQ ? Q_LR : KV_LR;
    const float* x = (isQ ? g_qc : g_kvc) + (size_t)row * (isQ ? Q_LR : KVC_D);
    __half* y      = (isQ ? g_qch : g_kvch) + (size_t)row * (isQ ? Q_LR : KV_LR);
    const float* gamma = isQ ? gamma_q : gamma_kv;
    const float* beta  = isQ ? beta_q  : beta_kv;

    float s = 0.f, s2 = 0.f;
    for (int i = threadIdx.x; i < D; i += 256) {
        float v = x[i];
        s += v; s2 += v * v;
    }
    __shared__ float shs[8], shs2[8];
#pragma unroll
    for (int o = 16; o > 0; o >>= 1) {
        s  += __shfl_down_sync(0xffffffffu, s,  o);
        s2 += __shfl_down_sync(0xffffffffu, s2, o);
    }
    int w = threadIdx.x >> 5, l = threadIdx.x & 31;
    if (l == 0) { shs[w] = s; shs2[w] = s2; }
    __syncthreads();
    if (w == 0) {
        s  = (l < 8) ? shs[l]  : 0.f;
        s2 = (l < 8) ? shs2[l] : 0.f;
#pragma unroll
        for (int o = 4; o > 0; o >>= 1) {
            s  += __shfl_down_sync(0xffffffffu, s,  o);
            s2 += __shfl_down_sync(0xffffffffu, s2, o);
        }
        if (l == 0) { shs[0] = s; shs2[0] = s2; }
    }
    __syncthreads();
    float mu  = shs[0] / D;
    float var = shs2[0] / D - mu * mu;
    float inv = rsqrtf(var + 1e-5f);

    for (int i = threadIdx.x; i < D; i += 256)
        y[i] = __float2half_rn((x[i] - mu) * inv * gamma[i] + beta[i]);

    if (!isQ) {
        // krope: rope(kvc[row, 512:576]) broadcast to 16 heads, cols 320..383
        int t  = threadIdx.x;
        int d  = t & 63;
        int dd = d & 31;
        int h0 = t >> 6;                       // 0..3
        int b  = row >> 12, ss = row & (Ss - 1);
        const float* tail = x + KV_LR;
        float x1 = tail[dd], x2 = tail[dd + 32];
        float c = g_cos[ss * 32 + dd], sn = g_sin[ss * 32 + dd];
        float val = (d < 32) ? (x1 * c - x2 * sn) : (x2 * c + x1 * sn);
#pragma unroll
        for (int hh = 0; hh < 4; ++hh) {
            int h = h0 + hh * 4;
            out[(((size_t)(b * NH + h) * Ss + ss) * OUT_D) + 320 + d] = val;
        }
    }
}

// ---------------------------------------------------------------------------
// Launch
// ---------------------------------------------------------------------------
extern "C" void kernel_launch(void* const* d_in, const int* /*in_sizes*/, int /*n_in*/,
                              void* d_out, int /*out_size*/)
{
    const float* hidden   = (const float*)d_in[0];
    const float* w_qa     = (const float*)d_in[1];
    const float* b_qa     = (const float*)d_in[2];
    const float* g_qa_ln  = (const float*)d_in[3];
    const float* b_qa_ln  = (const float*)d_in[4];
    const float* w_qb     = (const float*)d_in[5];
    const float* b_qb     = (const float*)d_in[6];
    const float* w_kva    = (const float*)d_in[7];
    const float* b_kva    = (const float*)d_in[8];
    const float* g_kva_ln = (const float*)d_in[9];
    const float* b_kva_ln = (const float*)d_in[10];
    const float* w_kvb    = (const float*)d_in[11];
    const float* b_kvb    = (const float*)d_in[12];
    float* out = (float*)d_out;

    float  *qc, *kvc;
    __half *qch, *kvch, *hidh, *wqah, *wqbh, *wkvah, *wkvbh;
    cudaGetSymbolAddress((void**)&qc,    g_qc);
    cudaGetSymbolAddress((void**)&kvc,   g_kvc);
    cudaGetSymbolAddress((void**)&qch,   g_qch);
    cudaGetSymbolAddress((void**)&kvch,  g_kvch);
    cudaGetSymbolAddress((void**)&hidh,  g_hidh);
    cudaGetSymbolAddress((void**)&wqah,  g_wqah);
    cudaGetSymbolAddress((void**)&wqbh,  g_wqbh);
    cudaGetSymbolAddress((void**)&wkvah, g_wkvah);
    cudaGetSymbolAddress((void**)&wkvbh, g_wkvbh);

    cudaFuncSetAttribute(gemm_mma_f16_dual,
                         cudaFuncAttributeMaxDynamicSharedMemorySize, GEMM_SMEM);

    // --- prep: rope table + all fp16 conversions, one launch ---
    prep_kernel<<<PREP_BLKS, 256>>>((const float4*)hidden,
                                    (const float4*)w_qa, (const float4*)w_kva,
                                    (const float4*)w_qb, (const float4*)w_kvb);

    const int mb = Mrows / BM;   // 64

    // --- fused G1 + G3: q_c and kv_c from hidden ---
    {
        GemmDesc d0{hidh, HID, wqah,  HID, b_qa,  qc,  Q_LR,  Q_LR,  HID, EPI_PLAIN};
        GemmDesc d1{hidh, HID, wkvah, HID, b_kva, kvc, KVC_D, KVC_D, HID, EPI_PLAIN};
        int nb0 = Q_LR / BN;                     // 6
        int nb1 = (KVC_D + BN - 1) / BN;         // 5
        gemm_mma_f16_dual<<<dim3(nb0 + nb1, mb), 256, GEMM_SMEM>>>(d0, d1, nb0);
    }

    // --- fused LN(qc) + LN(kvc) + krope ---
    ln_fused_kernel<<<2 * Mrows, 256>>>(g_qa_ln, b_qa_ln, g_kva_ln, b_kva_ln, out);

    // --- fused G2 + G4: q (RoPE-fused) and kv (scatter-fused) into out ---
    {
        GemmDesc d0{qch,  Q_LR,  wqbh,  Q_LR,  b_qb,  out, OUT_D, QD,  Q_LR,  EPI_Q};
        GemmDesc d1{kvch, KV_LR, wkvbh, KV_LR, b_kvb, out, OUT_D, KVD, KV_LR, EPI_KV};
        int nb0 = QD / BN;                       // 24
        int nb1 = KVD / BN;                      // 32
        gemm_mma_f16_dual<<<dim3(nb0 + nb1, mb), 256, GEMM_SMEM>>>(d0, d1, nb0);
    }
}

// round 15
// speedup vs baseline: 1.5702x; 1.0132x over previous
#include <cuda_runtime.h>
#include <cuda_fp16.h>
#include <cstdint>
#include <math.h>

// ---------------------------------------------------------------------------
// Problem constants
// ---------------------------------------------------------------------------
namespace {
constexpr int HID     = 2048;
constexpr int QK_NOPE = 128;
constexpr int QK_ROPE = 64;
constexpr int QK_HEAD = QK_NOPE + QK_ROPE;        // 192
constexpr int Q_LR    = 768;
constexpr int KV_LR   = 512;
constexpr int NH      = 16;
constexpr int V_DIM   = 128;
constexpr int Bb      = 2;
constexpr int Ss      = 4096;
constexpr int Mrows   = Bb * Ss;                  // 8192
constexpr int QD      = NH * QK_HEAD;             // 3072
constexpr int KVD     = NH * (QK_NOPE + V_DIM);   // 4096
constexpr int KVC_D   = KV_LR + QK_ROPE;          // 576
constexpr int OUT_D   = 512;
}

// ---------------------------------------------------------------------------
// Device scratch
// ---------------------------------------------------------------------------
__device__ float  g_qc  [Mrows * Q_LR];
__device__ float  g_kvc [Mrows * KVC_D];
__device__ __half g_qch [Mrows * Q_LR];
__device__ __half g_kvch[Mrows * KV_LR];
__device__ __half g_hidh[Mrows * HID];
__device__ __half g_wqah [Q_LR * HID];
__device__ __half g_wqbh [QD * Q_LR];
__device__ __half g_wkvah[KVC_D * HID];
__device__ __half g_wkvbh[KVD * KV_LR];
__device__ float  g_cos [Ss * 32];
__device__ float  g_sin [Ss * 32];

// ---------------------------------------------------------------------------
// Helpers
// ---------------------------------------------------------------------------
__device__ __forceinline__ uint32_t smem_u32(const void* p) {
    uint32_t a;
    asm("{ .reg .u64 t; cvta.to.shared.u64 t, %1; cvt.u32.u64 %0, t; }"
        : "=r"(a) : "l"(p));
    return a;
}

__device__ __forceinline__ void cp_async16(uint32_t dst, const void* src, bool valid) {
    int sz = valid ? 16 : 0;
    asm volatile("cp.async.ca.shared.global [%0], [%1], 16, %2;"
                 :: "r"(dst), "l"(src), "r"(sz) : "memory");
}
__device__ __forceinline__ void cp_commit() {
    asm volatile("cp.async.commit_group;" ::: "memory");
}
template <int N>
__device__ __forceinline__ void cp_wait() {
    asm volatile("cp.async.wait_group %0;" :: "n"(N) : "memory");
}

__device__ __forceinline__ void ldsm4(uint32_t& r0, uint32_t& r1,
                                      uint32_t& r2, uint32_t& r3, uint32_t addr) {
    asm volatile("ldmatrix.sync.aligned.m8n8.x4.shared.b16 {%0,%1,%2,%3}, [%4];"
                 : "=r"(r0), "=r"(r1), "=r"(r2), "=r"(r3) : "r"(addr));
}

__device__ __forceinline__ void mma16(float* c,
                                      uint32_t a0, uint32_t a1, uint32_t a2, uint32_t a3,
                                      uint32_t b0, uint32_t b1) {
    asm volatile(
        "mma.sync.aligned.m16n8k16.row.col.f32.f16.f16.f32 "
        "{%0,%1,%2,%3}, {%4,%5,%6,%7}, {%8,%9}, {%0,%1,%2,%3};"
        : "+f"(c[0]), "+f"(c[1]), "+f"(c[2]), "+f"(c[3])
        : "r"(a0), "r"(a1), "r"(a2), "r"(a3), "r"(b0), "r"(b1));
}

__device__ __forceinline__ void conv_chunk(const float4* __restrict__ src,
                                           uint2* __restrict__ dst, int chunk) {
    int base = chunk * 2048 + threadIdx.x;
#pragma unroll
    for (int j = 0; j < 8; ++j) {
        int idx = base + j * 256;
        float4 v = src[idx];
        __half2 h0 = __floats2half2_rn(v.x, v.y);
        __half2 h1 = __floats2half2_rn(v.z, v.w);
        dst[idx] = make_uint2(*(uint32_t*)&h0, *(uint32_t*)&h1);
    }
}

// ---------------------------------------------------------------------------
// GEMM config: block 128x128x64, 256 threads, 8 warps (4M x 2N), warp tile
// 32x64, 3-stage cp.async, 2 CTAs/SM.  Mainloop uses a one-ahead B-pair
// pipeline: each B ldmatrix is issued before the previous pair's 4 MMAs,
// with B fragments held in a 2x4 double buffer (8 regs vs 16) so ptxas has
// headroom to hoist next-kk A-loads as well.
// ---------------------------------------------------------------------------
namespace {
constexpr int BM = 128;
constexpr int BN = 128;
constexpr int BK = 64;                                // halves per K-iter
constexpr int NSTAGE = 3;
constexpr int LDSH = 72;                              // halves/row incl pad
constexpr int A_ST_H = BM * LDSH;
constexpr int B_ST_H = BN * LDSH;
constexpr int STAGE_H = A_ST_H + B_ST_H;              // 18432 halves
constexpr uint32_t GEMM_SMEM = NSTAGE * STAGE_H * 2;  // 110592 B
}

enum { EPI_PLAIN = 0, EPI_Q = 1, EPI_KV = 2 };

struct GemmDesc {
    const __half* A;  int lda;
    const __half* B;  int ldb;
    const float*  bias;
    float*        C;  int ldc;
    int N, K, mode;
};

// Two GEMMs fused in one launch: blockIdx.x < split -> d0, else d1.
__global__ void __launch_bounds__(256, 2)
gemm_mma_f16_dual(GemmDesc d0, GemmDesc d1, int split)
{
    extern __shared__ __half smh[];
    const uint32_t sm_b = smem_u32(smh);

    const GemmDesc& D = (blockIdx.x < (unsigned)split) ? d0 : d1;
    const int bn = ((blockIdx.x < (unsigned)split) ? blockIdx.x
                                                   : (blockIdx.x - split)) * BN;
    const __half* __restrict__ A = D.A;
    const __half* __restrict__ B = D.B;
    const int lda = D.lda, ldb = D.ldb, N = D.N, K = D.K, MODE = D.mode;

    const int tid  = threadIdx.x;
    const int wid  = tid >> 5;
    const int lane = tid & 31;
    const int wm   = wid & 3;
    const int wn   = wid >> 2;
    const int bm   = blockIdx.y * BM;
    const int m0   = wm * 32;
    const int n0   = wn * 64;
    const int qr   = lane >> 2;
    const int qc   = lane & 3;

    const int aRow  = m0 + (lane & 15);
    const int aKoff = (lane >> 4) * 8;
    const int bRow  = n0 + ((lane >> 4) & 1) * 8 + (lane & 7);
    const int bKoff = ((lane >> 3) & 1) * 8;

    float acc[2][8][4];
#pragma unroll
    for (int i = 0; i < 2; i++)
#pragma unroll
        for (int j = 0; j < 8; j++)
#pragma unroll
            for (int k = 0; k < 4; k++) acc[i][j][k] = 0.f;

    const int T = K / BK;

    auto issue_stage = [&](int t) {
        const int buf = t % NSTAGE;
        const uint32_t aBase = sm_b + (uint32_t)buf * STAGE_H * 2;
        const uint32_t bBase = aBase + A_ST_H * 2;
        const int k0 = t * BK;
#pragma unroll
        for (int j = 0; j < 4; ++j) {
            int i = j * 256 + tid;
            int r = i >> 3, c8 = i & 7;
            cp_async16(aBase + (uint32_t)(r * LDSH * 2 + c8 * 16),
                       A + (size_t)(bm + r) * lda + k0 + c8 * 8, true);
        }
#pragma unroll
        for (int j = 0; j < 4; ++j) {
            int i = j * 256 + tid;
            int r = i >> 3, c8 = i & 7;
            int n = bn + r;
            cp_async16(bBase + (uint32_t)(r * LDSH * 2 + c8 * 16),
                       B + (size_t)(n < N ? n : 0) * ldb + k0 + c8 * 8, n < N);
        }
        cp_commit();
    };

#pragma unroll
    for (int i = 0; i < NSTAGE - 1; ++i)
        if (i < T) issue_stage(i);

    for (int t = 0; t < T; ++t) {
        if (t < T - 1) cp_wait<NSTAGE - 2>(); else cp_wait<0>();
        __syncthreads();
        if (t + NSTAGE - 1 < T) issue_stage(t + NSTAGE - 1);

        const uint32_t As_u = sm_b + (uint32_t)(t % NSTAGE) * STAGE_H * 2;
        const uint32_t Bs_u = As_u + A_ST_H * 2;

#pragma unroll
        for (int kk = 0; kk < 4; ++kk) {
            const int kb = kk * 16;
            uint32_t a[2][4];
#pragma unroll
            for (int mf = 0; mf < 2; ++mf)
                ldsm4(a[mf][0], a[mf][1], a[mf][2], a[mf][3],
                      As_u + (uint32_t)((aRow + mf * 16) * LDSH + kb + aKoff) * 2);

            // one-ahead B-pair pipeline: bb[cur] feeds MMAs while bb[nxt] loads
            uint32_t bb[2][4];
            ldsm4(bb[0][0], bb[0][1], bb[0][2], bb[0][3],
                  Bs_u + (uint32_t)((bRow + 0 * 16) * LDSH + kb + bKoff) * 2);
#pragma unroll
            for (int nfp = 0; nfp < 4; ++nfp) {
                const int cur = nfp & 1;
                const int nxt = cur ^ 1;
                if (nfp < 3)
                    ldsm4(bb[nxt][0], bb[nxt][1], bb[nxt][2], bb[nxt][3],
                          Bs_u + (uint32_t)((bRow + (nfp + 1) * 16) * LDSH + kb + bKoff) * 2);
#pragma unroll
                for (int mf = 0; mf < 2; ++mf) {
                    mma16(acc[mf][2 * nfp],     a[mf][0], a[mf][1], a[mf][2], a[mf][3],
                          bb[cur][0], bb[cur][1]);
                    mma16(acc[mf][2 * nfp + 1], a[mf][0], a[mf][1], a[mf][2], a[mf][3],
                          bb[cur][2], bb[cur][3]);
                }
            }
        }
    }

    // -----------------------------------------------------------------------
    // Epilogues
    // -----------------------------------------------------------------------
    float* __restrict__ C = D.C;
    const float* __restrict__ bias = D.bias;
    const int ldc = D.ldc;

    if (MODE == EPI_PLAIN) {
#pragma unroll
        for (int nf = 0; nf < 8; ++nf) {
            int col = bn + n0 + nf * 8 + qc * 2;
            if (col >= N) continue;
            float2 bv = *(const float2*)(bias + col);
#pragma unroll
            for (int mf = 0; mf < 2; ++mf) {
                int r = bm + m0 + mf * 16 + qr;
                *(float2*)(C + (size_t)r * ldc + col) =
                    make_float2(acc[mf][nf][0] + bv.x, acc[mf][nf][1] + bv.y);
                *(float2*)(C + (size_t)(r + 8) * ldc + col) =
                    make_float2(acc[mf][nf][2] + bv.x, acc[mf][nf][3] + bv.y);
            }
        }
        return;
    }

    if (MODE == EPI_Q) {
        const int gn0  = bn + n0;
        const int h    = gn0 / QK_HEAD;
        const int w0   = gn0 % QK_HEAD;
        const bool rope = (w0 == 128);

        if (!rope) {
#pragma unroll
            for (int nf = 0; nf < 8; ++nf) {
                int col = gn0 + nf * 8 + qc * 2;
                float2 bv = *(const float2*)(bias + col);
                int oc = w0 + nf * 8 + qc * 2;
#pragma unroll
                for (int mf = 0; mf < 2; ++mf) {
#pragma unroll
                    for (int half = 0; half < 2; ++half) {
                        int r = bm + m0 + mf * 16 + qr + half * 8;
                        int b = r >> 12, s = r & (Ss - 1);
                        float* op = C + (((size_t)(b * NH + h) * Ss + s) * OUT_D) + oc;
                        *(float2*)op = make_float2(acc[mf][nf][half * 2]     + bv.x,
                                                   acc[mf][nf][half * 2 + 1] + bv.y);
                    }
                }
            }
        } else {
#pragma unroll
            for (int nf = 0; nf < 4; ++nf) {
                int d0  = nf * 8 + qc * 2;
                int col1 = gn0 + nf * 8 + qc * 2;
                int col2 = col1 + 32;
                float2 bv1 = *(const float2*)(bias + col1);
                float2 bv2 = *(const float2*)(bias + col2);
#pragma unroll
                for (int mf = 0; mf < 2; ++mf) {
#pragma unroll
                    for (int half = 0; half < 2; ++half) {
                        int r = bm + m0 + mf * 16 + qr + half * 8;
                        int b = r >> 12, s = r & (Ss - 1);
                        float ca = g_cos[s * 32 + d0],      sa = g_sin[s * 32 + d0];
                        float cbq = g_cos[s * 32 + d0 + 1], sbq = g_sin[s * 32 + d0 + 1];
                        float x1a = acc[mf][nf][half * 2]         + bv1.x;
                        float x1b = acc[mf][nf][half * 2 + 1]     + bv1.y;
                        float x2a = acc[mf][nf + 4][half * 2]     + bv2.x;
                        float x2b = acc[mf][nf + 4][half * 2 + 1] + bv2.y;
                        float* op = C + (((size_t)(b * NH + h) * Ss + s) * OUT_D);
                        *(float2*)(op + 128 + d0) =
                            make_float2(x1a * ca - x2a * sa, x1b * cbq - x2b * sbq);
                        *(float2*)(op + 160 + d0) =
                            make_float2(x2a * ca + x1a * sa, x2b * cbq + x1b * sbq);
                    }
                }
            }
        }
        return;
    }

    // MODE == EPI_KV
    {
#pragma unroll
        for (int nf = 0; nf < 8; ++nf) {
            int col = bn + n0 + nf * 8 + qc * 2;
            int h   = col >> 8;
            int cin = col & 255;
            float2 bv = *(const float2*)(bias + col);
            int oc = (cin < 128) ? (192 + cin) : (384 + (cin - 128));
#pragma unroll
            for (int mf = 0; mf < 2; ++mf) {
#pragma unroll
                for (int half = 0; half < 2; ++half) {
                    int r = bm + m0 + mf * 16 + qr + half * 8;
                    int b = r >> 12, s = r & (Ss - 1);
                    float* op = C + (((size_t)(b * NH + h) * Ss + s) * OUT_D) + oc;
                    *(float2*)op = make_float2(acc[mf][nf][half * 2]     + bv.x,
                                               acc[mf][nf][half * 2 + 1] + bv.y);
                }
            }
        }
    }
}

// ---------------------------------------------------------------------------
// Prep kernel: rope table + ALL fp16 conversions (hidden + 4 weights).
// ---------------------------------------------------------------------------
namespace {
constexpr int ROPE_BLKS = (Ss * 32) / 256;                   // 512
constexpr int HID_BLKS  = (Mrows * HID / 4) / 2048;          // 2048
constexpr int WQA_BLKS  = (Q_LR * HID / 4) / 2048;           // 192
constexpr int WKVA_BLKS = (KVC_D * HID / 4) / 2048;          // 144
constexpr int WQB_BLKS  = (QD * Q_LR / 4) / 2048;            // 288
constexpr int WKVB_BLKS = (KVD * KV_LR / 4) / 2048;          // 256
constexpr int PREP_BLKS = ROPE_BLKS + HID_BLKS + WQA_BLKS + WKVA_BLKS
                        + WQB_BLKS + WKVB_BLKS;
static_assert((Mrows * HID / 4) % 2048 == 0, "hid chunks");
static_assert((Q_LR * HID / 4) % 2048 == 0, "wqa chunks");
static_assert((KVC_D * HID / 4) % 2048 == 0, "wkva chunks");
static_assert((QD * Q_LR / 4) % 2048 == 0, "wqb chunks");
static_assert((KVD * KV_LR / 4) % 2048 == 0, "wkvb chunks");
}

__global__ void __launch_bounds__(256) prep_kernel(
    const float4* __restrict__ hidden,
    const float4* __restrict__ wqa,
    const float4* __restrict__ wkva,
    const float4* __restrict__ wqb,
    const float4* __restrict__ wkvb)
{
    int bid = blockIdx.x;
    if (bid < ROPE_BLKS) {
        int idx = bid * 256 + threadIdx.x;
        int dd = idx & 31;
        int s  = idx >> 5;
        float inv_freq = powf(10000.f, -(float)dd * (1.f / 32.f));
        float ang = (float)s * inv_freq;
        float sn, cs;
        sincosf(ang, &sn, &cs);
        g_cos[idx] = cs;
        g_sin[idx] = sn;
        return;
    }
    bid -= ROPE_BLKS;
    if (bid < HID_BLKS)  { conv_chunk(hidden, (uint2*)g_hidh, bid); return; }
    bid -= HID_BLKS;
    if (bid < WQA_BLKS)  { conv_chunk(wqa,  (uint2*)g_wqah,  bid); return; }
    bid -= WQA_BLKS;
    if (bid < WKVA_BLKS) { conv_chunk(wkva, (uint2*)g_wkvah, bid); return; }
    bid -= WKVA_BLKS;
    if (bid < WQB_BLKS)  { conv_chunk(wqb,  (uint2*)g_wqbh,  bid); return; }
    bid -= WQB_BLKS;
    conv_chunk(wkvb, (uint2*)g_wkvbh, bid);
}

// ---------------------------------------------------------------------------
// Fused LN kernel: bid < Mrows -> LN(qc) -> qch; else LN(kvc) -> kvch + krope.
// ---------------------------------------------------------------------------
__global__ void __launch_bounds__(256) ln_fused_kernel(
    const float* __restrict__ gamma_q, const float* __restrict__ beta_q,
    const float* __restrict__ gamma_kv, const float* __restrict__ beta_kv,
    float* __restrict__ out)
{
    const bool isQ = (blockIdx.x < (unsigned)Mrows);
    const int row  = isQ ? blockIdx.x : (blockIdx.x - Mrows);
    const int D    = isQ ? Q_LR : KV_LR;
    const float* x = (isQ ? g_qc : g_kvc) + (size_t)row * (isQ ? Q_LR : KVC_D);
    __half* y      = (isQ ? g_qch : g_kvch) + (size_t)row * (isQ ? Q_LR : KV_LR);
    const float* gamma = isQ ? gamma_q : gamma_kv;
    const float* beta  = isQ ? beta_q  : beta_kv;

    float s = 0.f, s2 = 0.f;
    for (int i = threadIdx.x; i < D; i += 256) {
        float v = x[i];
        s += v; s2 += v * v;
    }
    __shared__ float shs[8], shs2[8];
#pragma unroll
    for (int o = 16; o > 0; o >>= 1) {
        s  += __shfl_down_sync(0xffffffffu, s,  o);
        s2 += __shfl_down_sync(0xffffffffu, s2, o);
    }
    int w = threadIdx.x >> 5, l = threadIdx.x & 31;
    if (l == 0) { shs[w] = s; shs2[w] = s2; }
    __syncthreads();
    if (w == 0) {
        s  = (l < 8) ? shs[l]  : 0.f;
        s2 = (l < 8) ? shs2[l] : 0.f;
#pragma unroll
        for (int o = 4; o > 0; o >>= 1) {
            s  += __shfl_down_sync(0xffffffffu, s,  o);
            s2 += __shfl_down_sync(0xffffffffu, s2, o);
        }
        if (l == 0) { shs[0] = s; shs2[0] = s2; }
    }
    __syncthreads();
    float mu  = shs[0] / D;
    float var = shs2[0] / D - mu * mu;
    float inv = rsqrtf(var + 1e-5f);

    for (int i = threadIdx.x; i < D; i += 256)
        y[i] = __float2half_rn((x[i] - mu) * inv * gamma[i] + beta[i]);

    if (!isQ) {
        // krope: rope(kvc[row, 512:576]) broadcast to 16 heads, cols 320..383
        int t  = threadIdx.x;
        int d  = t & 63;
        int dd = d & 31;
        int h0 = t >> 6;                       // 0..3
        int b  = row >> 12, ss = row & (Ss - 1);
        const float* tail = x + KV_LR;
        float x1 = tail[dd], x2 = tail[dd + 32];
        float c = g_cos[ss * 32 + dd], sn = g_sin[ss * 32 + dd];
        float val = (d < 32) ? (x1 * c - x2 * sn) : (x2 * c + x1 * sn);
#pragma unroll
        for (int hh = 0; hh < 4; ++hh) {
            int h = h0 + hh * 4;
            out[(((size_t)(b * NH + h) * Ss + ss) * OUT_D) + 320 + d] = val;
        }
    }
}

// ---------------------------------------------------------------------------
// Launch
// ---------------------------------------------------------------------------
extern "C" void kernel_launch(void* const* d_in, const int* /*in_sizes*/, int /*n_in*/,
                              void* d_out, int /*out_size*/)
{
    const float* hidden   = (const float*)d_in[0];
    const float* w_qa     = (const float*)d_in[1];
    const float* b_qa     = (const float*)d_in[2];
    const float* g_qa_ln  = (const float*)d_in[3];
    const float* b_qa_ln  = (const float*)d_in[4];
    const float* w_qb     = (const float*)d_in[5];
    const float* b_qb     = (const float*)d_in[6];
    const float* w_kva    = (const float*)d_in[7];
    const float* b_kva    = (const float*)d_in[8];
    const float* g_kva_ln = (const float*)d_in[9];
    const float* b_kva_ln = (const float*)d_in[10];
    const float* w_kvb    = (const float*)d_in[11];
    const float* b_kvb    = (const float*)d_in[12];
    float* out = (float*)d_out;

    float  *qc, *kvc;
    __half *qch, *kvch, *hidh, *wqah, *wqbh, *wkvah, *wkvbh;
    cudaGetSymbolAddress((void**)&qc,    g_qc);
    cudaGetSymbolAddress((void**)&kvc,   g_kvc);
    cudaGetSymbolAddress((void**)&qch,   g_qch);
    cudaGetSymbolAddress((void**)&kvch,  g_kvch);
    cudaGetSymbolAddress((void**)&hidh,  g_hidh);
    cudaGetSymbolAddress((void**)&wqah,  g_wqah);
    cudaGetSymbolAddress((void**)&wqbh,  g_wqbh);
    cudaGetSymbolAddress((void**)&wkvah, g_wkvah);
    cudaGetSymbolAddress((void**)&wkvbh, g_wkvbh);

    cudaFuncSetAttribute(gemm_mma_f16_dual,
                         cudaFuncAttributeMaxDynamicSharedMemorySize, GEMM_SMEM);

    // --- prep: rope table + all fp16 conversions, one launch ---
    prep_kernel<<<PREP_BLKS, 256>>>((const float4*)hidden,
                                    (const float4*)w_qa, (const float4*)w_kva,
                                    (const float4*)w_qb, (const float4*)w_kvb);

    const int mb = Mrows / BM;   // 64

    // --- fused G1 + G3: q_c and kv_c from hidden ---
    {
        GemmDesc d0{hidh, HID, wqah,  HID, b_qa,  qc,  Q_LR,  Q_LR,  HID, EPI_PLAIN};
        GemmDesc d1{hidh, HID, wkvah, HID, b_kva, kvc, KVC_D, KVC_D, HID, EPI_PLAIN};
        int nb0 = Q_LR / BN;                     // 6
        int nb1 = (KVC_D + BN - 1) / BN;         // 5
        gemm_mma_f16_dual<<<dim3(nb0 + nb1, mb), 256, GEMM_SMEM>>>(d0, d1, nb0);
    }

    // --- fused LN(qc) + LN(kvc) + krope ---
    ln_fused_kernel<<<2 * Mrows, 256>>>(g_qa_ln, b_qa_ln, g_kva_ln, b_kva_ln, out);

    // --- fused G2 + G4: q (RoPE-fused) and kv (scatter-fused) into out ---
    {
        GemmDesc d0{qch,  Q_LR,  wqbh,  Q_LR,  b_qb,  out, OUT_D, QD,  Q_LR,  EPI_Q};
        GemmDesc d1{kvch, KV_LR, wkvbh, KV_LR, b_kvb, out, OUT_D, KVD, KV_LR, EPI_KV};
        int nb0 = QD / BN;                       // 24
        int nb1 = KVD / BN;                      // 32
        gemm_mma_f16_dual<<<dim3(nb0 + nb1, mb), 256, GEMM_SMEM>>>(d0, d1, nb0);
    }
}